// round 2
// baseline (speedup 1.0000x reference)
#include <cuda_runtime.h>

// Problem constants (fixed by the dataset)
#define HH   512
#define WW   512
#define KK   51
#define PADK 25           // K//2
#define PR   562          // padded extent (512 + 2*25)
#define PSTR 576          // padded row stride (16B-aligned float4 rows)
#define HWSZ (512*512)

// Pre-padded frames: [frame(0/2)][batch][channel][row][col]
// 2*2*3*562*576 floats = 15.5 MB. Static device scratch (no allocations).
__device__ __align__(16) float g_pad[2][2][3][PR][PSTR];

// ---------------------------------------------------------------------------
// Pad kernel: replication-pad both frames into g_pad. Cheap (~31 MB traffic).
// ---------------------------------------------------------------------------
__global__ void pad_kernel(const float* __restrict__ f0,
                           const float* __restrict__ f2) {
    long idx = (long)blockIdx.x * blockDim.x + threadIdx.x;
    const long total = 2L * 2 * 3 * PR * PSTR;
    if (idx >= total) return;
    int col = (int)(idx % PSTR);
    long r  = idx / PSTR;
    int row = (int)(r % PR); r /= PR;
    int c   = (int)(r % 3);  r /= 3;
    int b   = (int)(r % 2);  r /= 2;
    int f   = (int)r;
    int sy = row - PADK; sy = sy < 0 ? 0 : (sy > HH - 1 ? HH - 1 : sy);
    int sx = col - PADK; sx = sx < 0 ? 0 : (sx > WW - 1 ? WW - 1 : sx);
    const float* src = f ? f2 : f0;
    g_pad[f][b][c][row][col] = src[((size_t)(b * 3 + c) * HH + sy) * WW + sx];
}

// ---------------------------------------------------------------------------
// One 17-tap horizontal chunk, all 51 vertical taps, all 3 channels, 4 outputs.
// JBASE in {0,17,34}. Hk taps for this chunk are held in registers (float4,
// one component per output t). P windows are aligned float4 loads from g_pad.
// ---------------------------------------------------------------------------
template<int JBASE>
__device__ __forceinline__ void chunk_pass(
    const float* __restrict__ Hf,     // H plane base for (frame,batch)
    const float* __restrict__ Vf,     // V plane base for (frame,batch)
    const float* __restrict__ padB,   // &g_pad[f][b][0][0][0]
    int y, int x0, float acc[3][4])
{
    constexpr int PHI = JBASE & 3;               // misalignment phase 0/1/2
    constexpr int NL  = (PHI + 20 + 3) / 4;      // float4 loads per window (5 or 6)

    // Load 17 taps x 4 outputs of Hk once per chunk (coalesced LDG.128).
    float4 hk[17];
    #pragma unroll
    for (int j = 0; j < 17; j++)
        hk[j] = *reinterpret_cast<const float4*>(
            Hf + (size_t)(JBASE + j) * HWSZ + (size_t)y * WW + x0);

    const int col0 = x0 + (JBASE & ~3);          // aligned window start

    #pragma unroll 1
    for (int i = 0; i < KK; i++) {
        // V taps for this row (coalesced LDG.128), hoisted to overlap latency
        float4 v4 = *reinterpret_cast<const float4*>(
            Vf + (size_t)i * HWSZ + (size_t)y * WW + x0);

        float hsum[3][4];
        #pragma unroll
        for (int c = 0; c < 3; c++)
            #pragma unroll
            for (int t = 0; t < 4; t++) hsum[c][t] = 0.0f;

        #pragma unroll
        for (int c = 0; c < 3; c++) {
            const float* prow = padB + ((size_t)c * PR + (y + i)) * PSTR + col0;
            float p[NL * 4];
            #pragma unroll
            for (int q = 0; q < NL; q++) {
                float4 t4 = reinterpret_cast<const float4*>(prow)[q];
                p[4*q+0] = t4.x; p[4*q+1] = t4.y;
                p[4*q+2] = t4.z; p[4*q+3] = t4.w;
            }
            // jj = t + j' (j' = tap within chunk). 68 FMAs per channel.
            #pragma unroll
            for (int jj = 0; jj < 20; jj++) {
                float pv = p[PHI + jj];
                #pragma unroll
                for (int t = 0; t < 4; t++) {
                    if (jj - t >= 0 && jj - t <= 16) {
                        float hv = (t == 0) ? hk[jj - t].x :
                                   (t == 1) ? hk[jj - t].y :
                                   (t == 2) ? hk[jj - t].z : hk[jj - t].w;
                        hsum[c][t] += pv * hv;
                    }
                }
            }
        }

        // Fold in the vertical tap
        #pragma unroll
        for (int c = 0; c < 3; c++) {
            acc[c][0] += v4.x * hsum[c][0];
            acc[c][1] += v4.y * hsum[c][1];
            acc[c][2] += v4.z * hsum[c][2];
            acc[c][3] += v4.w * hsum[c][3];
        }
    }
}

// ---------------------------------------------------------------------------
// Main kernel: one block per (y, b); 128 threads x 4 outputs = full row.
// ---------------------------------------------------------------------------
__global__ void __launch_bounds__(128, 3) sepconv_kernel(
    const float* __restrict__ V1, const float* __restrict__ H1,
    const float* __restrict__ V2, const float* __restrict__ H2,
    float* __restrict__ out)
{
    const int y  = blockIdx.x;
    const int b  = blockIdx.y;
    const int x0 = threadIdx.x * 4;

    float acc[3][4];
    #pragma unroll
    for (int c = 0; c < 3; c++)
        #pragma unroll
        for (int t = 0; t < 4; t++) acc[c][t] = 0.0f;

    #pragma unroll 1
    for (int f = 0; f < 2; f++) {
        const float* Vf   = (f ? V2 : V1) + (size_t)b * KK * HWSZ;
        const float* Hf   = (f ? H2 : H1) + (size_t)b * KK * HWSZ;
        const float* padB = &g_pad[f][b][0][0][0];
        chunk_pass<0 >(Hf, Vf, padB, y, x0, acc);
        chunk_pass<17>(Hf, Vf, padB, y, x0, acc);
        chunk_pass<34>(Hf, Vf, padB, y, x0, acc);
    }

    #pragma unroll
    for (int c = 0; c < 3; c++) {
        float4 o;
        o.x = acc[c][0]; o.y = acc[c][1]; o.z = acc[c][2]; o.w = acc[c][3];
        *reinterpret_cast<float4*>(
            out + ((size_t)(b * 3 + c) * HH + y) * WW + x0) = o;
    }
}

// ---------------------------------------------------------------------------
// kernel_launch: inputs are frame0, frame2, V1, H1, V2, H2 (metadata order).
// ---------------------------------------------------------------------------
extern "C" void kernel_launch(void* const* d_in, const int* in_sizes, int n_in,
                              void* d_out, int out_size) {
    const float* frame0 = (const float*)d_in[0];
    const float* frame2 = (const float*)d_in[1];
    const float* V1     = (const float*)d_in[2];
    const float* H1     = (const float*)d_in[3];
    const float* V2     = (const float*)d_in[4];
    const float* H2     = (const float*)d_in[5];
    float* out = (float*)d_out;

    const long total = 2L * 2 * 3 * PR * PSTR;
    pad_kernel<<<(int)((total + 255) / 256), 256>>>(frame0, frame2);

    dim3 grid(HH, 2);
    sepconv_kernel<<<grid, 128>>>(V1, H1, V2, H2, out);
}

// round 4
// speedup vs baseline: 1.0962x; 1.0962x over previous
#include <cuda_runtime.h>

// Problem constants (fixed by the dataset)
#define HH   512
#define WW   512
#define KK   51
#define PADK 25           // K//2
#define PR   562          // padded extent (512 + 2*25)
#define PSTR 576          // padded row stride (16B-aligned float4 rows)
#define HWSZ (512*512)

// Pre-padded frames: [frame(0/2)][batch][channel][row][col]  (15.5 MB scratch)
__device__ __align__(16) float g_pad[2][2][3][PR][PSTR];

// ---------------------------------------------------------------------------
// Pad kernel: replication-pad both frames into g_pad.
// ---------------------------------------------------------------------------
__global__ void pad_kernel(const float* __restrict__ f0,
                           const float* __restrict__ f2) {
    long idx = (long)blockIdx.x * blockDim.x + threadIdx.x;
    const long total = 2L * 2 * 3 * PR * PSTR;
    if (idx >= total) return;
    int col = (int)(idx % PSTR);
    long r  = idx / PSTR;
    int row = (int)(r % PR); r /= PR;
    int c   = (int)(r % 3);  r /= 3;
    int b   = (int)(r % 2);  r /= 2;
    int f   = (int)r;
    int sy = row - PADK; sy = sy < 0 ? 0 : (sy > HH - 1 ? HH - 1 : sy);
    int sx = col - PADK; sx = sx < 0 ? 0 : (sx > WW - 1 ? WW - 1 : sx);
    const float* src = f ? f2 : f0;
    g_pad[f][b][c][row][col] = src[((size_t)(b * 3 + c) * HH + sy) * WW + sx];
}

// ---------------------------------------------------------------------------
// cp.async helpers
// ---------------------------------------------------------------------------
__device__ __forceinline__ void cp_async16(void* smem_dst, const void* gmem_src) {
    unsigned saddr = (unsigned)__cvta_generic_to_shared(smem_dst);
    asm volatile("cp.async.cg.shared.global [%0], [%1], 16;\n"
                 :: "r"(saddr), "l"(gmem_src));
}
__device__ __forceinline__ void cp_commit() {
    asm volatile("cp.async.commit_group;\n" ::: "memory");
}
__device__ __forceinline__ void cp_wait_all() {
    asm volatile("cp.async.wait_group 0;\n" ::: "memory");
}

// Stage one padded row (3 channels x 576 floats = 432 float4) into smem buffer.
__device__ __forceinline__ void stage_row(float (*dst)[PSTR],
                                          const float* __restrict__ padB,
                                          int row, int tid) {
    #pragma unroll
    for (int k = 0; k < 4; k++) {
        int idx = tid + k * 128;               // 0..511, need < 432
        if (idx < 432) {
            int c = idx / 144;                 // 144 float4 per channel row
            int q = idx - c * 144;
            const float4* src = reinterpret_cast<const float4*>(
                padB + ((size_t)c * PR + row) * PSTR) + q;
            cp_async16(&dst[c][q * 4], src);
        }
    }
    cp_commit();
}

// ---------------------------------------------------------------------------
// One 17-tap horizontal chunk, all 51 vertical taps, 3 channels, 4 outputs.
// P rows are staged through shared memory (double-buffered cp.async).
// ---------------------------------------------------------------------------
template<int JBASE>
__device__ __forceinline__ void chunk_pass(
    const float* __restrict__ Hf,
    const float* __restrict__ Vf,
    const float* __restrict__ padB,
    float (*sbuf)[3][PSTR],            // [2][3][PSTR] double buffer
    int y, int x0, int tid, float acc[3][4])
{
    constexpr int PHI = JBASE & 3;                 // misalignment phase
    constexpr int NL  = (PHI + 20 + 3) / 4;        // float4 loads per window

    // 17 taps x 4 outputs of Hk in registers (coalesced LDG.128, reused 51x).
    float4 hk[17];
    #pragma unroll
    for (int j = 0; j < 17; j++)
        hk[j] = *reinterpret_cast<const float4*>(
            Hf + (size_t)(JBASE + j) * HWSZ + (size_t)y * WW + x0);

    const int col0 = x0 + (JBASE & ~3);            // aligned window start

    // Prologue: stage row y into buffer 0
    stage_row(sbuf[0], padB, y, tid);
    cp_wait_all();
    __syncthreads();

    #pragma unroll 1
    for (int i = 0; i < KK; i++) {
        const int cur = i & 1;
        // Prefetch next row under this iteration's compute
        if (i < KK - 1)
            stage_row(sbuf[cur ^ 1], padB, y + i + 1, tid);

        // V taps for this row (coalesced LDG.128, consumed late -> hidden)
        float4 v4 = *reinterpret_cast<const float4*>(
            Vf + (size_t)i * HWSZ + (size_t)y * WW + x0);

        float hsum[3][4];
        #pragma unroll
        for (int c = 0; c < 3; c++)
            #pragma unroll
            for (int t = 0; t < 4; t++) hsum[c][t] = 0.0f;

        #pragma unroll
        for (int c = 0; c < 3; c++) {
            const float* prow = &sbuf[cur][c][col0];
            float p[NL * 4];
            #pragma unroll
            for (int q = 0; q < NL; q++) {
                float4 t4 = reinterpret_cast<const float4*>(prow)[q];  // LDS.128
                p[4*q+0] = t4.x; p[4*q+1] = t4.y;
                p[4*q+2] = t4.z; p[4*q+3] = t4.w;
            }
            #pragma unroll
            for (int jj = 0; jj < 20; jj++) {
                float pv = p[PHI + jj];
                #pragma unroll
                for (int t = 0; t < 4; t++) {
                    if (jj - t >= 0 && jj - t <= 16) {
                        float hv = (t == 0) ? hk[jj - t].x :
                                   (t == 1) ? hk[jj - t].y :
                                   (t == 2) ? hk[jj - t].z : hk[jj - t].w;
                        hsum[c][t] += pv * hv;
                    }
                }
            }
        }

        #pragma unroll
        for (int c = 0; c < 3; c++) {
            acc[c][0] += v4.x * hsum[c][0];
            acc[c][1] += v4.y * hsum[c][1];
            acc[c][2] += v4.z * hsum[c][2];
            acc[c][3] += v4.w * hsum[c][3];
        }

        cp_wait_all();        // next-row copy landed
        __syncthreads();      // everyone done reading cur / copy visible
    }
}

// ---------------------------------------------------------------------------
// Main kernel: one block per (y, b); 128 threads x 4 outputs = full row.
// ---------------------------------------------------------------------------
__global__ void __launch_bounds__(128, 3) sepconv_kernel(
    const float* __restrict__ V1, const float* __restrict__ H1,
    const float* __restrict__ V2, const float* __restrict__ H2,
    float* __restrict__ out)
{
    __shared__ __align__(16) float sbuf[2][3][PSTR];   // 13.8 KB

    const int y   = blockIdx.x;
    const int b   = blockIdx.y;
    const int tid = threadIdx.x;
    const int x0  = tid * 4;

    float acc[3][4];
    #pragma unroll
    for (int c = 0; c < 3; c++)
        #pragma unroll
        for (int t = 0; t < 4; t++) acc[c][t] = 0.0f;

    #pragma unroll 1
    for (int f = 0; f < 2; f++) {
        const float* Vf   = (f ? V2 : V1) + (size_t)b * KK * HWSZ;
        const float* Hf   = (f ? H2 : H1) + (size_t)b * KK * HWSZ;
        const float* padB = &g_pad[f][b][0][0][0];
        chunk_pass<0 >(Hf, Vf, padB, sbuf, y, x0, tid, acc);
        chunk_pass<17>(Hf, Vf, padB, sbuf, y, x0, tid, acc);
        chunk_pass<34>(Hf, Vf, padB, sbuf, y, x0, tid, acc);
    }

    #pragma unroll
    for (int c = 0; c < 3; c++) {
        float4 o;
        o.x = acc[c][0]; o.y = acc[c][1]; o.z = acc[c][2]; o.w = acc[c][3];
        *reinterpret_cast<float4*>(
            out + ((size_t)(b * 3 + c) * HH + y) * WW + x0) = o;
    }
}

// ---------------------------------------------------------------------------
// kernel_launch: inputs are frame0, frame2, V1, H1, V2, H2 (metadata order).
// ---------------------------------------------------------------------------
extern "C" void kernel_launch(void* const* d_in, const int* in_sizes, int n_in,
                              void* d_out, int out_size) {
    const float* frame0 = (const float*)d_in[0];
    const float* frame2 = (const float*)d_in[1];
    const float* V1     = (const float*)d_in[2];
    const float* H1     = (const float*)d_in[3];
    const float* V2     = (const float*)d_in[4];
    const float* H2     = (const float*)d_in[5];
    float* out = (float*)d_out;

    const long total = 2L * 2 * 3 * PR * PSTR;
    pad_kernel<<<(int)((total + 255) / 256), 256>>>(frame0, frame2);

    dim3 grid(HH, 2);
    sepconv_kernel<<<grid, 128>>>(V1, H1, V2, H2, out);
}